// round 12
// baseline (speedup 1.0000x reference)
#include <cuda_runtime.h>
#include <stdint.h>

// Problem constants (fixed by setup_inputs):
//   kv_cache: (NUM_LAYERS=8, 2, B=4, H=8, L=2048, D=128) fp32
//   new_kv:   (8, 2, 4, 8, 1, 128) fp32
//   position_ids: (4, 1) — stored as int32 (JAX x64 disabled downcasts int64)
//   seq_len = 1024
// out = kv_cache[..., :1024, :] with row s==pos[b] replaced by new_kv.
//
// FINAL (R4 config, reproduced R11): single fused streaming kernel.
//   - one float4 store per output element, fully coalesced both streams
//   - MLP_p1=2 per thread (R6: MLP=4 regresses via cross-CTA L1tex-queue
//     spread; R8: .cs hints <= neutral; R9: copy engine 3.3x slower)
//   - scatter fused as a predicated overwrite on the rare matching row
// Measured: 75.5-76.1us kernel, 6.36-6.42 TB/s (~78% of spec) — at the
// path-independent LTS-cap plateau for a 1:1 fp32 read:write stream.
// Traffic is minimal (512 MB total); no further SM- or CE-side lever exists.

#define L_FULL   2048
#define S_OUT    1024
#define D_DIM    128
#define B_DIM    4
#define ROWBLKS  512            // 8 * 2 * 4 * 8  (l,kv,b,h) combined
#define F4_PER_ROW   (D_DIM / 4)        // 32
#define F4_PER_BLK_OUT (S_OUT * F4_PER_ROW)   // 32768
#define F4_PER_BLK_IN  (L_FULL * F4_PER_ROW)  // 65536
#define TOTAL_F4 (ROWBLKS * F4_PER_BLK_OUT)   // 16,777,216

#define THREADS   256
#define F4_PER_THREAD 2
#define GRID      (TOTAL_F4 / (THREADS * F4_PER_THREAD))   // 32768 blocks

__global__ void __launch_bounds__(THREADS)
kv_slice_update_kernel(const float4* __restrict__ cache,
                       const float4* __restrict__ newkv,
                       const int* __restrict__ pos,
                       float4* __restrict__ out)
{
    const unsigned base = blockIdx.x * (THREADS * F4_PER_THREAD) + threadIdx.x;

    float4 v[F4_PER_THREAD];

#pragma unroll
    for (int j = 0; j < F4_PER_THREAD; ++j) {
        const unsigned i4 = base + j * THREADS;
        const unsigned d4     = i4 & (F4_PER_ROW - 1);
        const unsigned s      = (i4 >> 5) & (S_OUT - 1);
        const unsigned rowblk = i4 >> 15;
        v[j] = __ldg(&cache[(size_t)rowblk * F4_PER_BLK_IN
                            + (size_t)s * F4_PER_ROW + d4]);
    }

#pragma unroll
    for (int j = 0; j < F4_PER_THREAD; ++j) {
        const unsigned i4     = base + j * THREADS;
        const unsigned d4     = i4 & (F4_PER_ROW - 1);
        const unsigned s      = (i4 >> 5) & (S_OUT - 1);
        const unsigned rowblk = i4 >> 15;
        const unsigned b      = (rowblk >> 3) & (B_DIM - 1);
        const int p = __ldg(&pos[b]);
        if ((int)s == p) {
            v[j] = __ldg(&newkv[rowblk * F4_PER_ROW + d4]);
        }
        out[i4] = v[j];
    }
}

extern "C" void kernel_launch(void* const* d_in, const int* in_sizes, int n_in,
                              void* d_out, int out_size)
{
    const float4* cache = (const float4*)d_in[0];
    const float4* newkv = (const float4*)d_in[1];
    const int*    pos   = (const int*)d_in[2];
    float4*       out   = (float4*)d_out;

    kv_slice_update_kernel<<<GRID, THREADS>>>(cache, newkv, pos, out);
}